// round 13
// baseline (speedup 1.0000x reference)
#include <cuda_runtime.h>
#include <cstdint>

using u32 = unsigned int;

#define Sc 2048
#define NT 256
#define BR 64
#define NTILES 16
#define LOG2E 1.4426950408889634f

// smem (bytes), total 81920 -> 2 CTAs/SM:
//  QH 0 (8KB), QL 8192 (8KB)           Q bf16 splits, 64x64
//  KH 16384, KL 32768, VH 49152, VL 65536   (each 16KB: 128x64 bf16)
// epilogue aliases: MRG_O @0 (float[64][64]=16KB), MM @KH, ML @KH+256
#define QH_OFF 0
#define QL_OFF 8192
#define KH_OFF 16384
#define KL_OFF 32768
#define VH_OFF 49152
#define VL_OFF 65536
#define SMEM_BYTES 81920
#define MRG_O 0
#define MRG_M KH_OFF
#define MRG_L (KH_OFF + 256)

__device__ __forceinline__ u32 swz(u32 x) { return x ^ ((x >> 3) & 0x70); }
__device__ __forceinline__ u32 smem_u32(const void* p) {
    u32 a;
    asm("{ .reg .u64 t; cvta.to.shared.u64 t, %1; cvt.u32.u64 %0, t; }" : "=r"(a) : "l"(p));
    return a;
}
__device__ __forceinline__ u32 packbf2(float lo, float hi) {   // lo -> low half
    u32 d; asm("cvt.rn.bf16x2.f32 %0, %1, %2;" : "=r"(d) : "f"(hi), "f"(lo)); return d;
}
__device__ __forceinline__ float bf_lo(u32 p) { return __uint_as_float(p << 16); }
__device__ __forceinline__ float bf_hi(u32 p) { return __uint_as_float(p & 0xffff0000u); }
__device__ __forceinline__ void split2(float a, float b, u32& h, u32& l) {
    h = packbf2(a, b);
    l = packbf2(a - bf_lo(h), b - bf_hi(h));
}
__device__ __forceinline__ float ex2a(float x) {
    float r; asm("ex2.approx.ftz.f32 %0, %1;" : "=f"(r) : "f"(x)); return r;
}
__device__ __forceinline__ void ldsm4(u32& r0, u32& r1, u32& r2, u32& r3, u32 a) {
    asm volatile("ldmatrix.sync.aligned.m8n8.x4.shared.b16 {%0,%1,%2,%3}, [%4];"
                 : "=r"(r0), "=r"(r1), "=r"(r2), "=r"(r3) : "r"(a));
}
__device__ __forceinline__ void ldsm4t(u32& r0, u32& r1, u32& r2, u32& r3, u32 a) {
    asm volatile("ldmatrix.sync.aligned.m8n8.x4.trans.shared.b16 {%0,%1,%2,%3}, [%4];"
                 : "=r"(r0), "=r"(r1), "=r"(r2), "=r"(r3) : "r"(a));
}
__device__ __forceinline__ void mma_bf16(float* d, u32 a0, u32 a1, u32 a2, u32 a3, u32 b0, u32 b1) {
    asm volatile("mma.sync.aligned.m16n8k16.row.col.f32.bf16.bf16.f32 "
                 "{%0,%1,%2,%3}, {%4,%5,%6,%7}, {%8,%9}, {%0,%1,%2,%3};"
                 : "+f"(d[0]), "+f"(d[1]), "+f"(d[2]), "+f"(d[3])
                 : "r"(a0), "r"(a1), "r"(a2), "r"(a3), "r"(b0), "r"(b1));
}

// load K/V tile (128x64 fp32 each) -> bf16 split tiles in stage (streamed)
__device__ __forceinline__ void load_kv(char* smc, int tid, const float* Kt, const float* Vt) {
    #pragma unroll 2
    for (int it = 0; it < 8; ++it) {
        int i = tid + NT * it;
        int r = i >> 4, c4 = i & 15;
        u32 off = swz((u32)(r * 128 + c4 * 8));
        float4 kv = ((const float4*)Kt)[i];
        u32 h0, l0, h1, l1;
        split2(kv.x, kv.y, h0, l0);
        split2(kv.z, kv.w, h1, l1);
        *(uint2*)(smc + KH_OFF + off) = make_uint2(h0, h1);
        *(uint2*)(smc + KL_OFF + off) = make_uint2(l0, l1);
        float4 vv = ((const float4*)Vt)[i];
        split2(vv.x, vv.y, h0, l0);
        split2(vv.z, vv.w, h1, l1);
        *(uint2*)(smc + VH_OFF + off) = make_uint2(h0, h1);
        *(uint2*)(smc + VL_OFF + off) = make_uint2(l0, l1);
    }
}

__global__ void __launch_bounds__(NT, 2)
attn_mma(const float* __restrict__ Q, const float* __restrict__ K,
         const float* __restrict__ V, const int* __restrict__ Mask,
         float* __restrict__ Out)
{
    extern __shared__ char smc[];
    const u32 sb = smem_u32(smc);
    const int tid  = threadIdx.x;
    const int wid  = tid >> 5;
    const int lane = tid & 31;
    const int gid  = lane >> 2;
    const int tig  = lane & 3;
    const int wq   = wid & 3;     // q-row block (4 x 16 rows = 64)
    const int ch   = wid >> 2;    // key-column half (0: k 0-63, 1: k 64-127)

    const int bh = blockIdx.y;
    const int b  = bh >> 4;
    const int q0 = blockIdx.x * BR;

    const float* Qg = Q + ((size_t)bh * Sc + q0) * 64;
    const float* Kg = K + (size_t)bh * Sc * 64;
    const float* Vg = V + (size_t)bh * Sc * 64;
    const int*   Mg = Mask + (size_t)b * Sc * Sc + (size_t)q0 * Sc;
    float*       Og = Out + ((size_t)bh * Sc + q0) * 64;

    // ---- Q -> smem bf16 splits (64x64) ----
    #pragma unroll
    for (int it = 0; it < 4; ++it) {
        int i = tid + NT * it;               // float4 over [64][16]
        int r = i >> 4, c4 = i & 15;
        float4 v = ((const float4*)Qg)[i];
        u32 off = swz((u32)(r * 128 + c4 * 8));
        u32 h0, l0, h1, l1;
        split2(v.x, v.y, h0, l0);
        split2(v.z, v.w, h1, l1);
        *(uint2*)(smc + QH_OFF + off) = make_uint2(h0, h1);
        *(uint2*)(smc + QL_OFF + off) = make_uint2(l0, l1);
    }

    // ---- stage tile 0 ----
    load_kv(smc, tid, Kg, Vg);
    __syncthreads();

    // ldmatrix per-lane address components
    const u32 aRB  = (u32)(16 * wq + (lane & 7) + ((lane >> 3) & 1) * 8) * 128;
    const u32 aKH  = (u32)(lane >> 4) * 16;
    const int bRow = (((lane >> 4) & 1) << 3) + (lane & 7);
    const u32 bKH  = (u32)((lane >> 3) & 1) * 16;
    const int vRow = (((lane >> 3) & 1) << 3) + (lane & 7);
    const u32 vDB  = (u32)(lane >> 4) * 16;
    const int kBase = 64 * ch;

    const int row0 = 16 * wq + gid;
    const int row1 = row0 + 8;
    const int* M0 = Mg + (size_t)row0 * Sc;
    const int* M1 = Mg + (size_t)row1 * Sc;

    float O[8][4];
    #pragma unroll
    for (int n = 0; n < 8; ++n)
        #pragma unroll
        for (int c = 0; c < 4; ++c) O[n][c] = 0.0f;
    float m0 = -1e30f, m1 = -1e30f, l0 = 0.0f, l1 = 0.0f;

    for (int kt = 0; kt < NTILES; ++kt) {
        // ---- S = Q K^T over this warp's 64 key-cols ----
        float s[8][4];
        #pragma unroll
        for (int n = 0; n < 8; ++n)
            #pragma unroll
            for (int c = 0; c < 4; ++c) s[n][c] = 0.0f;

        #pragma unroll
        for (int k4 = 0; k4 < 4; ++k4) {
            u32 qoff = swz(aRB + (u32)k4 * 32 + aKH);
            u32 qh0, qh1, qh2, qh3, ql0, ql1, ql2, ql3;
            ldsm4(qh0, qh1, qh2, qh3, sb + QH_OFF + qoff);
            ldsm4(ql0, ql1, ql2, ql3, sb + QL_OFF + qoff);
            #pragma unroll
            for (int np = 0; np < 4; ++np) {
                u32 boff = swz((u32)(kBase + 16 * np + bRow) * 128 + (u32)k4 * 32 + bKH);
                u32 bh0, bh1, bh2, bh3, bl0, bl1, bl2, bl3;
                ldsm4(bh0, bh1, bh2, bh3, sb + KH_OFF + boff);
                ldsm4(bl0, bl1, bl2, bl3, sb + KL_OFF + boff);
                mma_bf16(s[2 * np],     qh0, qh1, qh2, qh3, bh0, bh1);
                mma_bf16(s[2 * np + 1], qh0, qh1, qh2, qh3, bh2, bh3);
                mma_bf16(s[2 * np],     ql0, ql1, ql2, ql3, bh0, bh1);
                mma_bf16(s[2 * np + 1], ql0, ql1, ql2, ql3, bh2, bh3);
                mma_bf16(s[2 * np],     qh0, qh1, qh2, qh3, bl0, bl1);
                mma_bf16(s[2 * np + 1], qh0, qh1, qh2, qh3, bl2, bl3);
            }
        }

        // ---- mask + scale + online softmax (warp-local col-half) ----
        const int cb = kt * 128 + kBase + 2 * tig;
        float mx0 = -1e30f, mx1 = -1e30f;
        #pragma unroll
        for (int n = 0; n < 8; ++n) {
            int2 ma = *(const int2*)(M0 + cb + 8 * n);
            int2 mb = *(const int2*)(M1 + cb + 8 * n);
            s[n][0] = ma.x ? s[n][0] * 0.125f : -32768.0f;
            s[n][1] = ma.y ? s[n][1] * 0.125f : -32768.0f;
            s[n][2] = mb.x ? s[n][2] * 0.125f : -32768.0f;
            s[n][3] = mb.y ? s[n][3] * 0.125f : -32768.0f;
            mx0 = fmaxf(mx0, fmaxf(s[n][0], s[n][1]));
            mx1 = fmaxf(mx1, fmaxf(s[n][2], s[n][3]));
        }
        mx0 = fmaxf(mx0, __shfl_xor_sync(0xffffffffu, mx0, 1));
        mx0 = fmaxf(mx0, __shfl_xor_sync(0xffffffffu, mx0, 2));
        mx1 = fmaxf(mx1, __shfl_xor_sync(0xffffffffu, mx1, 1));
        mx1 = fmaxf(mx1, __shfl_xor_sync(0xffffffffu, mx1, 2));

        float mn0 = fmaxf(m0, mx0), mn1 = fmaxf(m1, mx1);
        float alpha0 = ex2a((m0 - mn0) * LOG2E);
        float alpha1 = ex2a((m1 - mn1) * LOG2E);
        m0 = mn0; m1 = mn1;

        float sum0 = 0.0f, sum1 = 0.0f;
        #pragma unroll
        for (int n = 0; n < 8; ++n) {
            float p0 = ex2a((s[n][0] - mn0) * LOG2E);
            float p1 = ex2a((s[n][1] - mn0) * LOG2E);
            float p2 = ex2a((s[n][2] - mn1) * LOG2E);
            float p3 = ex2a((s[n][3] - mn1) * LOG2E);
            s[n][0] = p0; s[n][1] = p1; s[n][2] = p2; s[n][3] = p3;
            sum0 += p0 + p1; sum1 += p2 + p3;
        }
        sum0 += __shfl_xor_sync(0xffffffffu, sum0, 1);
        sum0 += __shfl_xor_sync(0xffffffffu, sum0, 2);
        sum1 += __shfl_xor_sync(0xffffffffu, sum1, 1);
        sum1 += __shfl_xor_sync(0xffffffffu, sum1, 2);
        l0 = l0 * alpha0 + sum0;
        l1 = l1 * alpha1 + sum1;

        #pragma unroll
        for (int n = 0; n < 8; ++n) {
            O[n][0] *= alpha0; O[n][1] *= alpha0;
            O[n][2] *= alpha1; O[n][3] *= alpha1;
        }

        // ---- O += P V over this warp's 64 key-rows of V ----
        #pragma unroll
        for (int kk = 0; kk < 4; ++kk) {
            u32 ah0 = packbf2(s[2 * kk][0],     s[2 * kk][1]);
            u32 ah1 = packbf2(s[2 * kk][2],     s[2 * kk][3]);
            u32 ah2 = packbf2(s[2 * kk + 1][0], s[2 * kk + 1][1]);
            u32 ah3 = packbf2(s[2 * kk + 1][2], s[2 * kk + 1][3]);
            u32 al0 = packbf2(s[2 * kk][0] - bf_lo(ah0),     s[2 * kk][1] - bf_hi(ah0));
            u32 al1 = packbf2(s[2 * kk][2] - bf_lo(ah1),     s[2 * kk][3] - bf_hi(ah1));
            u32 al2 = packbf2(s[2 * kk + 1][0] - bf_lo(ah2), s[2 * kk + 1][1] - bf_hi(ah2));
            u32 al3 = packbf2(s[2 * kk + 1][2] - bf_lo(ah3), s[2 * kk + 1][3] - bf_hi(ah3));
            u32 vro = (u32)(kBase + 16 * kk + vRow) * 128;
            #pragma unroll
            for (int np = 0; np < 4; ++np) {
                u32 voff = swz(vro + (u32)np * 32 + vDB);
                u32 vh0, vh1, vh2, vh3, vl0, vl1, vl2, vl3;
                ldsm4t(vh0, vh1, vh2, vh3, sb + VH_OFF + voff);
                ldsm4t(vl0, vl1, vl2, vl3, sb + VL_OFF + voff);
                mma_bf16(O[2 * np],     ah0, ah1, ah2, ah3, vh0, vh1);
                mma_bf16(O[2 * np + 1], ah0, ah1, ah2, ah3, vh2, vh3);
                mma_bf16(O[2 * np],     al0, al1, al2, al3, vh0, vh1);
                mma_bf16(O[2 * np + 1], al0, al1, al2, al3, vh2, vh3);
                mma_bf16(O[2 * np],     ah0, ah1, ah2, ah3, vl0, vl1);
                mma_bf16(O[2 * np + 1], ah0, ah1, ah2, ah3, vl2, vl3);
            }
        }

        __syncthreads();   // all stage reads done
        if (kt < NTILES - 1) {
            load_kv(smc, tid, Kg + (size_t)(kt + 1) * 128 * 64, Vg + (size_t)(kt + 1) * 128 * 64);
            __syncthreads();   // stage writes visible
        }
    }

    // ---- epilogue: merge col-halves (split-k combine), write ----
    float* MO = (float*)(smc + MRG_O);
    float* MM = (float*)(smc + MRG_M);
    float* ML = (float*)(smc + MRG_L);
    if (ch == 1) {
        if (tig == 0) {
            MM[row0] = m0; ML[row0] = l0;
            MM[row1] = m1; ML[row1] = l1;
        }
        #pragma unroll
        for (int n = 0; n < 8; ++n) {
            MO[row0 * 64 + 8 * n + 2 * tig]     = O[n][0];
            MO[row0 * 64 + 8 * n + 2 * tig + 1] = O[n][1];
            MO[row1 * 64 + 8 * n + 2 * tig]     = O[n][2];
            MO[row1 * 64 + 8 * n + 2 * tig + 1] = O[n][3];
        }
    }
    __syncthreads();
    if (ch == 0) {
        float mB0 = MM[row0], lB0 = ML[row0];
        float mB1 = MM[row1], lB1 = ML[row1];
        float mf0 = fmaxf(m0, mB0), mf1 = fmaxf(m1, mB1);
        float a0 = ex2a((m0 - mf0) * LOG2E), b0 = ex2a((mB0 - mf0) * LOG2E);
        float a1 = ex2a((m1 - mf1) * LOG2E), b1 = ex2a((mB1 - mf1) * LOG2E);
        float inv0 = 1.0f / (l0 * a0 + lB0 * b0);
        float inv1 = 1.0f / (l1 * a1 + lB1 * b1);
        float* o0 = Og + (size_t)row0 * 64 + 2 * tig;
        float* o1 = Og + (size_t)row1 * 64 + 2 * tig;
        #pragma unroll
        for (int n = 0; n < 8; ++n) {
            float w0 = (O[n][0] * a0 + MO[row0 * 64 + 8 * n + 2 * tig]     * b0) * inv0;
            float w1 = (O[n][1] * a0 + MO[row0 * 64 + 8 * n + 2 * tig + 1] * b0) * inv0;
            float w2 = (O[n][2] * a1 + MO[row1 * 64 + 8 * n + 2 * tig]     * b1) * inv1;
            float w3 = (O[n][3] * a1 + MO[row1 * 64 + 8 * n + 2 * tig + 1] * b1) * inv1;
            *(float2*)(o0 + 8 * n) = make_float2(w0, w1);
            *(float2*)(o1 + 8 * n) = make_float2(w2, w3);
        }
    }
}

extern "C" void kernel_launch(void* const* d_in, const int* in_sizes, int n_in,
                              void* d_out, int out_size)
{
    const float* Q    = (const float*)d_in[0];
    const float* K    = (const float*)d_in[1];
    const float* V    = (const float*)d_in[2];
    const int*   mask = (const int*)d_in[3];
    float* out = (float*)d_out;

    cudaFuncSetAttribute(attn_mma, cudaFuncAttributeMaxDynamicSharedMemorySize, SMEM_BYTES);
    dim3 grid(Sc / BR, 32);
    attn_mma<<<grid, NT, SMEM_BYTES>>>(Q, K, V, mask, out);
}

// round 14
// speedup vs baseline: 1.0637x; 1.0637x over previous
#include <cuda_runtime.h>
#include <cstdint>

using u32 = unsigned int;

#define Sc 2048
#define NT 512
#define NTILES 16
#define LOG2E 1.4426950408889634f

// main-kernel smem: QH 0, QL 16384 (Q bf16 splits, 128x64)
// stage s at STG_OFF + s*STG_SZ: KH +0, KL +16384, VH +32768, VL +49152
#define QH_OFF 0
#define QL_OFF 16384
#define STG_OFF 32768
#define STG_SZ  65536
#define SMEM_BYTES (STG_OFF + 2 * STG_SZ)   /* 163840 */
// epilogue merge buffers alias stage 0
#define MRG_O STG_OFF
#define MRG_M (STG_OFF + 32768)
#define MRG_L (STG_OFF + 33280)

// pre-split, pre-swizzled K/V tiles: [bh][kt] -> 16384 bytes each
#define TILE_B 16384
__device__ static unsigned char KHg[32 * 16 * TILE_B];
__device__ static unsigned char KLg[32 * 16 * TILE_B];
__device__ static unsigned char VHg[32 * 16 * TILE_B];
__device__ static unsigned char VLg[32 * 16 * TILE_B];

__device__ __forceinline__ u32 swz(u32 x) { return x ^ ((x >> 3) & 0x70); }
__device__ __forceinline__ u32 smem_u32(const void* p) {
    u32 a;
    asm("{ .reg .u64 t; cvta.to.shared.u64 t, %1; cvt.u32.u64 %0, t; }" : "=r"(a) : "l"(p));
    return a;
}
__device__ __forceinline__ u32 packbf2(float lo, float hi) {   // lo -> low half
    u32 d; asm("cvt.rn.bf16x2.f32 %0, %1, %2;" : "=r"(d) : "f"(hi), "f"(lo)); return d;
}
__device__ __forceinline__ float bf_lo(u32 p) { return __uint_as_float(p << 16); }
__device__ __forceinline__ float bf_hi(u32 p) { return __uint_as_float(p & 0xffff0000u); }
__device__ __forceinline__ void split2(float a, float b, u32& h, u32& l) {
    h = packbf2(a, b);
    l = packbf2(a - bf_lo(h), b - bf_hi(h));
}
__device__ __forceinline__ float ex2a(float x) {
    float r; asm("ex2.approx.ftz.f32 %0, %1;" : "=f"(r) : "f"(x)); return r;
}
__device__ __forceinline__ void ldsm4(u32& r0, u32& r1, u32& r2, u32& r3, u32 a) {
    asm volatile("ldmatrix.sync.aligned.m8n8.x4.shared.b16 {%0,%1,%2,%3}, [%4];"
                 : "=r"(r0), "=r"(r1), "=r"(r2), "=r"(r3) : "r"(a));
}
__device__ __forceinline__ void ldsm4t(u32& r0, u32& r1, u32& r2, u32& r3, u32 a) {
    asm volatile("ldmatrix.sync.aligned.m8n8.x4.trans.shared.b16 {%0,%1,%2,%3}, [%4];"
                 : "=r"(r0), "=r"(r1), "=r"(r2), "=r"(r3) : "r"(a));
}
__device__ __forceinline__ void mma_bf16(float* d, u32 a0, u32 a1, u32 a2, u32 a3, u32 b0, u32 b1) {
    asm volatile("mma.sync.aligned.m16n8k16.row.col.f32.bf16.bf16.f32 "
                 "{%0,%1,%2,%3}, {%4,%5,%6,%7}, {%8,%9}, {%0,%1,%2,%3};"
                 : "+f"(d[0]), "+f"(d[1]), "+f"(d[2]), "+f"(d[3])
                 : "r"(a0), "r"(a1), "r"(a2), "r"(a3), "r"(b0), "r"(b1));
}
__device__ __forceinline__ void cpa16(u32 dst, const void* src) {
    asm volatile("cp.async.cg.shared.global [%0], [%1], 16;" :: "r"(dst), "l"(src));
}
#define CP_COMMIT() asm volatile("cp.async.commit_group;" ::: "memory")
#define CP_WAIT0()  asm volatile("cp.async.wait_group 0;" ::: "memory")

// ---------------- prologue: split + pre-swizzle K/V into gmem scratch ----------------
__global__ void __launch_bounds__(256)
preconv(const float* __restrict__ K, const float* __restrict__ V)
{
    const int kt = blockIdx.x;    // 0..15
    const int bh = blockIdx.y;    // 0..31
    const int tid = threadIdx.x;
    const size_t toff = ((size_t)bh * 16 + kt) * TILE_B;
    const float4* Kt = (const float4*)(K + ((size_t)bh * Sc + kt * 128) * 64);
    const float4* Vt = (const float4*)(V + ((size_t)bh * Sc + kt * 128) * 64);

    #pragma unroll
    for (int it = 0; it < 8; ++it) {
        int i = tid + 256 * it;            // float4 over [128 rows][16]
        int r = i >> 4, c4 = i & 15;
        u32 off = swz((u32)(r * 128 + c4 * 8));
        float4 kv = Kt[i];
        u32 h0, l0, h1, l1;
        split2(kv.x, kv.y, h0, l0);
        split2(kv.z, kv.w, h1, l1);
        *(uint2*)(KHg + toff + off) = make_uint2(h0, h1);
        *(uint2*)(KLg + toff + off) = make_uint2(l0, l1);
        float4 vv = Vt[i];
        split2(vv.x, vv.y, h0, l0);
        split2(vv.z, vv.w, h1, l1);
        *(uint2*)(VHg + toff + off) = make_uint2(h0, h1);
        *(uint2*)(VLg + toff + off) = make_uint2(l0, l1);
    }
}

// cp.async one pre-split tile set (64KB) into stage at smem addr sbst
__device__ __forceinline__ void load_stage(u32 sbst, int tid, size_t toff) {
    #pragma unroll
    for (int half = 0; half < 2; ++half) {
        u32 ci = ((u32)tid + 512u * half) * 16u;
        cpa16(sbst + 0     + ci, KHg + toff + ci);
        cpa16(sbst + 16384 + ci, KLg + toff + ci);
        cpa16(sbst + 32768 + ci, VHg + toff + ci);
        cpa16(sbst + 49152 + ci, VLg + toff + ci);
    }
}

// ---------------- main kernel (geometry/softmax identical to R8 best) ----------------
__global__ void __launch_bounds__(NT, 1)
attn_mma(const float* __restrict__ Q, const float* __restrict__ K,
         const float* __restrict__ V, const int* __restrict__ Mask,
         float* __restrict__ Out)
{
    extern __shared__ char smc[];
    const u32 sb = smem_u32(smc);
    const int tid  = threadIdx.x;
    const int wid  = tid >> 5;
    const int lane = tid & 31;
    const int gid  = lane >> 2;
    const int tig  = lane & 3;
    const int wq   = wid & 7;     // q-row block (8 x 16 rows)
    const int ch   = wid >> 3;    // key-column half

    const int bh = blockIdx.y;
    const int b  = bh >> 4;
    const int q0 = blockIdx.x * 128;

    const float* Qg = Q + ((size_t)bh * Sc + q0) * 64;
    const int*   Mg = Mask + (size_t)b * Sc * Sc + (size_t)q0 * Sc;
    float*       Og = Out + ((size_t)bh * Sc + q0) * 64;
    const size_t tbase = (size_t)bh * 16 * TILE_B;

    // ---- Q -> smem bf16 splits ----
    #pragma unroll
    for (int it = 0; it < 4; ++it) {
        int i = tid + NT * it;
        int r = i >> 4, c4 = i & 15;
        float4 v = ((const float4*)Qg)[i];
        u32 off = swz((u32)(r * 128 + c4 * 8));
        u32 h0, l0, h1, l1;
        split2(v.x, v.y, h0, l0);
        split2(v.z, v.w, h1, l1);
        *(uint2*)(smc + QH_OFF + off) = make_uint2(h0, h1);
        *(uint2*)(smc + QL_OFF + off) = make_uint2(l0, l1);
    }

    // ---- stage tile 0 ----
    load_stage(sb + STG_OFF, tid, tbase);
    CP_COMMIT();

    // ldmatrix per-lane address components
    const u32 aRB  = (u32)(16 * wq + (lane & 7) + ((lane >> 3) & 1) * 8) * 128;
    const u32 aKH  = (u32)(lane >> 4) * 16;
    const int bRow = (((lane >> 4) & 1) << 3) + (lane & 7);
    const u32 bKH  = (u32)((lane >> 3) & 1) * 16;
    const int vRow = (((lane >> 3) & 1) << 3) + (lane & 7);
    const u32 vDB  = (u32)(lane >> 4) * 16;
    const int kBase = 64 * ch;

    const int row0 = 16 * wq + gid;
    const int row1 = row0 + 8;
    const int* M0 = Mg + (size_t)row0 * Sc;
    const int* M1 = Mg + (size_t)row1 * Sc;

    CP_WAIT0();
    __syncthreads();   // Q smem + stage 0 visible

    float O[8][4];
    #pragma unroll
    for (int n = 0; n < 8; ++n)
        #pragma unroll
        for (int c = 0; c < 4; ++c) O[n][c] = 0.0f;
    float m0 = -1e30f, m1 = -1e30f, l0 = 0.0f, l1 = 0.0f;

    int stg = 0;

    for (int kt = 0; kt < NTILES; ++kt) {
        const u32 stq  = sb + STG_OFF + (u32)stg * STG_SZ;
        const u32 stqn = sb + STG_OFF + (u32)(stg ^ 1) * STG_SZ;

        // (i) prefetch next pre-split tile into other stage
        if (kt < NTILES - 1) {
            load_stage(stqn, tid, tbase + (size_t)(kt + 1) * TILE_B);
            CP_COMMIT();
        }

        // (ii) S = Q K^T over this warp's 64 key-cols
        float s[8][4];
        #pragma unroll
        for (int n = 0; n < 8; ++n)
            #pragma unroll
            for (int c = 0; c < 4; ++c) s[n][c] = 0.0f;

        #pragma unroll
        for (int k4 = 0; k4 < 4; ++k4) {
            u32 qoff = swz(aRB + (u32)k4 * 32 + aKH);
            u32 qh0, qh1, qh2, qh3, ql0, ql1, ql2, ql3;
            ldsm4(qh0, qh1, qh2, qh3, sb + QH_OFF + qoff);
            ldsm4(ql0, ql1, ql2, ql3, sb + QL_OFF + qoff);
            #pragma unroll
            for (int np = 0; np < 4; ++np) {
                u32 boff = swz((u32)(kBase + 16 * np + bRow) * 128 + (u32)k4 * 32 + bKH);
                u32 bh0, bh1, bh2, bh3, bl0, bl1, bl2, bl3;
                ldsm4(bh0, bh1, bh2, bh3, stq + 0     + boff);
                ldsm4(bl0, bl1, bl2, bl3, stq + 16384 + boff);
                mma_bf16(s[2 * np],     qh0, qh1, qh2, qh3, bh0, bh1);
                mma_bf16(s[2 * np + 1], qh0, qh1, qh2, qh3, bh2, bh3);
                mma_bf16(s[2 * np],     ql0, ql1, ql2, ql3, bh0, bh1);
                mma_bf16(s[2 * np + 1], ql0, ql1, ql2, ql3, bh2, bh3);
                mma_bf16(s[2 * np],     qh0, qh1, qh2, qh3, bl0, bl1);
                mma_bf16(s[2 * np + 1], qh0, qh1, qh2, qh3, bl2, bl3);
            }
        }

        // (iii) mask + scale + online softmax (warp-local col-half)
        const int cb = kt * 128 + kBase + 2 * tig;
        float mx0 = -1e30f, mx1 = -1e30f;
        #pragma unroll
        for (int n = 0; n < 8; ++n) {
            int2 ma = *(const int2*)(M0 + cb + 8 * n);
            int2 mb = *(const int2*)(M1 + cb + 8 * n);
            s[n][0] = ma.x ? s[n][0] * 0.125f : -32768.0f;
            s[n][1] = ma.y ? s[n][1] * 0.125f : -32768.0f;
            s[n][2] = mb.x ? s[n][2] * 0.125f : -32768.0f;
            s[n][3] = mb.y ? s[n][3] * 0.125f : -32768.0f;
            mx0 = fmaxf(mx0, fmaxf(s[n][0], s[n][1]));
            mx1 = fmaxf(mx1, fmaxf(s[n][2], s[n][3]));
        }
        mx0 = fmaxf(mx0, __shfl_xor_sync(0xffffffffu, mx0, 1));
        mx0 = fmaxf(mx0, __shfl_xor_sync(0xffffffffu, mx0, 2));
        mx1 = fmaxf(mx1, __shfl_xor_sync(0xffffffffu, mx1, 1));
        mx1 = fmaxf(mx1, __shfl_xor_sync(0xffffffffu, mx1, 2));

        float mn0 = fmaxf(m0, mx0), mn1 = fmaxf(m1, mx1);
        float alpha0 = ex2a((m0 - mn0) * LOG2E);
        float alpha1 = ex2a((m1 - mn1) * LOG2E);
        m0 = mn0; m1 = mn1;

        float sum0 = 0.0f, sum1 = 0.0f;
        #pragma unroll
        for (int n = 0; n < 8; ++n) {
            float p0 = ex2a((s[n][0] - mn0) * LOG2E);
            float p1 = ex2a((s[n][1] - mn0) * LOG2E);
            float p2 = ex2a((s[n][2] - mn1) * LOG2E);
            float p3 = ex2a((s[n][3] - mn1) * LOG2E);
            s[n][0] = p0; s[n][1] = p1; s[n][2] = p2; s[n][3] = p3;
            sum0 += p0 + p1; sum1 += p2 + p3;
        }
        sum0 += __shfl_xor_sync(0xffffffffu, sum0, 1);
        sum0 += __shfl_xor_sync(0xffffffffu, sum0, 2);
        sum1 += __shfl_xor_sync(0xffffffffu, sum1, 1);
        sum1 += __shfl_xor_sync(0xffffffffu, sum1, 2);
        l0 = l0 * alpha0 + sum0;
        l1 = l1 * alpha1 + sum1;

        #pragma unroll
        for (int n = 0; n < 8; ++n) {
            O[n][0] *= alpha0; O[n][1] *= alpha0;
            O[n][2] *= alpha1; O[n][3] *= alpha1;
        }

        // (iv) O += P V over this warp's 64 key-rows of V
        #pragma unroll
        for (int kk = 0; kk < 4; ++kk) {
            u32 ah0 = packbf2(s[2 * kk][0],     s[2 * kk][1]);
            u32 ah1 = packbf2(s[2 * kk][2],     s[2 * kk][3]);
            u32 ah2 = packbf2(s[2 * kk + 1][0], s[2 * kk + 1][1]);
            u32 ah3 = packbf2(s[2 * kk + 1][2], s[2 * kk + 1][3]);
            u32 al0 = packbf2(s[2 * kk][0] - bf_lo(ah0),     s[2 * kk][1] - bf_hi(ah0));
            u32 al1 = packbf2(s[2 * kk][2] - bf_lo(ah1),     s[2 * kk][3] - bf_hi(ah1));
            u32 al2 = packbf2(s[2 * kk + 1][0] - bf_lo(ah2), s[2 * kk + 1][1] - bf_hi(ah2));
            u32 al3 = packbf2(s[2 * kk + 1][2] - bf_lo(ah3), s[2 * kk + 1][3] - bf_hi(ah3));
            u32 vro = (u32)(kBase + 16 * kk + vRow) * 128;
            #pragma unroll
            for (int np = 0; np < 4; ++np) {
                u32 voff = swz(vro + (u32)np * 32 + vDB);
                u32 vh0, vh1, vh2, vh3, vl0, vl1, vl2, vl3;
                ldsm4t(vh0, vh1, vh2, vh3, stq + 32768 + voff);
                ldsm4t(vl0, vl1, vl2, vl3, stq + 49152 + voff);
                mma_bf16(O[2 * np],     ah0, ah1, ah2, ah3, vh0, vh1);
                mma_bf16(O[2 * np + 1], ah0, ah1, ah2, ah3, vh2, vh3);
                mma_bf16(O[2 * np],     al0, al1, al2, al3, vh0, vh1);
                mma_bf16(O[2 * np + 1], al0, al1, al2, al3, vh2, vh3);
                mma_bf16(O[2 * np],     ah0, ah1, ah2, ah3, vl0, vl1);
                mma_bf16(O[2 * np + 1], ah0, ah1, ah2, ah3, vl2, vl3);
            }
        }

        // (v) wait prefetch + single barrier per tile
        if (kt < NTILES - 1) CP_WAIT0();
        __syncthreads();
        stg ^= 1;
    }

    // ---- epilogue: merge col-halves (split-k combine), write ----
    float* MO = (float*)(smc + MRG_O);
    float* MM = (float*)(smc + MRG_M);
    float* ML = (float*)(smc + MRG_L);
    if (ch == 1) {
        if (tig == 0) {
            MM[row0] = m0; ML[row0] = l0;
            MM[row1] = m1; ML[row1] = l1;
        }
        #pragma unroll
        for (int n = 0; n < 8; ++n) {
            MO[row0 * 64 + 8 * n + 2 * tig]     = O[n][0];
            MO[row0 * 64 + 8 * n + 2 * tig + 1] = O[n][1];
            MO[row1 * 64 + 8 * n + 2 * tig]     = O[n][2];
            MO[row1 * 64 + 8 * n + 2 * tig + 1] = O[n][3];
        }
    }
    __syncthreads();
    if (ch == 0) {
        float mB0 = MM[row0], lB0 = ML[row0];
        float mB1 = MM[row1], lB1 = ML[row1];
        float mf0 = fmaxf(m0, mB0), mf1 = fmaxf(m1, mB1);
        float a0 = ex2a((m0 - mf0) * LOG2E), b0 = ex2a((mB0 - mf0) * LOG2E);
        float a1 = ex2a((m1 - mf1) * LOG2E), b1 = ex2a((mB1 - mf1) * LOG2E);
        float inv0 = 1.0f / (l0 * a0 + lB0 * b0);
        float inv1 = 1.0f / (l1 * a1 + lB1 * b1);
        float* o0 = Og + (size_t)row0 * 64 + 2 * tig;
        float* o1 = Og + (size_t)row1 * 64 + 2 * tig;
        #pragma unroll
        for (int n = 0; n < 8; ++n) {
            float w0 = (O[n][0] * a0 + MO[row0 * 64 + 8 * n + 2 * tig]     * b0) * inv0;
            float w1 = (O[n][1] * a0 + MO[row0 * 64 + 8 * n + 2 * tig + 1] * b0) * inv0;
            float w2 = (O[n][2] * a1 + MO[row1 * 64 + 8 * n + 2 * tig]     * b1) * inv1;
            float w3 = (O[n][3] * a1 + MO[row1 * 64 + 8 * n + 2 * tig + 1] * b1) * inv1;
            *(float2*)(o0 + 8 * n) = make_float2(w0, w1);
            *(float2*)(o1 + 8 * n) = make_float2(w2, w3);
        }
    }
}

extern "C" void kernel_launch(void* const* d_in, const int* in_sizes, int n_in,
                              void* d_out, int out_size)
{
    const float* Q    = (const float*)d_in[0];
    const float* K    = (const float*)d_in[1];
    const float* V    = (const float*)d_in[2];
    const int*   mask = (const int*)d_in[3];
    float* out = (float*)d_out;

    preconv<<<dim3(16, 32), 256>>>(K, V);

    cudaFuncSetAttribute(attn_mma, cudaFuncAttributeMaxDynamicSharedMemorySize, SMEM_BYTES);
    dim3 grid(Sc / 128, 32);
    attn_mma<<<grid, NT, SMEM_BYTES>>>(Q, K, V, mask, out);
}

// round 15
// speedup vs baseline: 1.1979x; 1.1262x over previous
#include <cuda_runtime.h>
#include <cstdint>

using u32 = unsigned int;

#define Sc 2048
#define NT 512
#define NTILES 16
#define LOG2E 1.4426950408889634f

// main-kernel smem: QH 0, QL 16384 (Q bf16 splits, 128x64)
// stage s at STG_OFF + s*STG_SZ: KH +0, KL +16384, VH +32768, VL +49152, MB +65536 (2KB)
#define QH_OFF 0
#define QL_OFF 16384
#define STG_OFF 32768
#define STG_SZ  67584
#define SMEM_BYTES (STG_OFF + 2 * STG_SZ)   /* 167936 */
// epilogue merge buffers alias stage 0
#define MRG_O STG_OFF
#define MRG_M (STG_OFF + 32768)
#define MRG_L (STG_OFF + 33280)

// pre-split, pre-swizzled K/V tiles: [bh][kt] -> 16384 bytes each
#define TILE_B 16384
__device__ static unsigned char KHg[32 * 16 * TILE_B];
__device__ static unsigned char KLg[32 * 16 * TILE_B];
__device__ static unsigned char VHg[32 * 16 * TILE_B];
__device__ static unsigned char VLg[32 * 16 * TILE_B];
// mask bitmaps: [b][qt][kt] -> 128 rows x 4 u32 = 2048 bytes
#define MTILE_B 2048
__device__ static unsigned char MBg[2 * 16 * 16 * MTILE_B];

__device__ __forceinline__ u32 swz(u32 x) { return x ^ ((x >> 3) & 0x70); }
__device__ __forceinline__ u32 smem_u32(const void* p) {
    u32 a;
    asm("{ .reg .u64 t; cvta.to.shared.u64 t, %1; cvt.u32.u64 %0, t; }" : "=r"(a) : "l"(p));
    return a;
}
__device__ __forceinline__ u32 packbf2(float lo, float hi) {   // lo -> low half
    u32 d; asm("cvt.rn.bf16x2.f32 %0, %1, %2;" : "=r"(d) : "f"(hi), "f"(lo)); return d;
}
__device__ __forceinline__ float bf_lo(u32 p) { return __uint_as_float(p << 16); }
__device__ __forceinline__ float bf_hi(u32 p) { return __uint_as_float(p & 0xffff0000u); }
__device__ __forceinline__ void split2(float a, float b, u32& h, u32& l) {
    h = packbf2(a, b);
    l = packbf2(a - bf_lo(h), b - bf_hi(h));
}
__device__ __forceinline__ float ex2a(float x) {
    float r; asm("ex2.approx.ftz.f32 %0, %1;" : "=f"(r) : "f"(x)); return r;
}
__device__ __forceinline__ void ldsm4(u32& r0, u32& r1, u32& r2, u32& r3, u32 a) {
    asm volatile("ldmatrix.sync.aligned.m8n8.x4.shared.b16 {%0,%1,%2,%3}, [%4];"
                 : "=r"(r0), "=r"(r1), "=r"(r2), "=r"(r3) : "r"(a));
}
__device__ __forceinline__ void ldsm4t(u32& r0, u32& r1, u32& r2, u32& r3, u32 a) {
    asm volatile("ldmatrix.sync.aligned.m8n8.x4.trans.shared.b16 {%0,%1,%2,%3}, [%4];"
                 : "=r"(r0), "=r"(r1), "=r"(r2), "=r"(r3) : "r"(a));
}
__device__ __forceinline__ void mma_bf16(float* d, u32 a0, u32 a1, u32 a2, u32 a3, u32 b0, u32 b1) {
    asm volatile("mma.sync.aligned.m16n8k16.row.col.f32.bf16.bf16.f32 "
                 "{%0,%1,%2,%3}, {%4,%5,%6,%7}, {%8,%9}, {%0,%1,%2,%3};"
                 : "+f"(d[0]), "+f"(d[1]), "+f"(d[2]), "+f"(d[3])
                 : "r"(a0), "r"(a1), "r"(a2), "r"(a3), "r"(b0), "r"(b1));
}
__device__ __forceinline__ void cpa16(u32 dst, const void* src) {
    asm volatile("cp.async.cg.shared.global [%0], [%1], 16;" :: "r"(dst), "l"(src));
}
#define CP_COMMIT() asm volatile("cp.async.commit_group;" ::: "memory")
#define CP_WAIT0()  asm volatile("cp.async.wait_group 0;" ::: "memory")

// ---------------- prologue 1: split + pre-swizzle K/V into gmem scratch ----------------
__global__ void __launch_bounds__(256)
preconv(const float* __restrict__ K, const float* __restrict__ V)
{
    const int kt = blockIdx.x;    // 0..15
    const int bh = blockIdx.y;    // 0..31
    const int tid = threadIdx.x;
    const size_t toff = ((size_t)bh * 16 + kt) * TILE_B;
    const float4* Kt = (const float4*)(K + ((size_t)bh * Sc + kt * 128) * 64);
    const float4* Vt = (const float4*)(V + ((size_t)bh * Sc + kt * 128) * 64);

    #pragma unroll
    for (int it = 0; it < 8; ++it) {
        int i = tid + 256 * it;            // float4 over [128 rows][16]
        int r = i >> 4, c4 = i & 15;
        u32 off = swz((u32)(r * 128 + c4 * 8));
        float4 kv = Kt[i];
        u32 h0, l0, h1, l1;
        split2(kv.x, kv.y, h0, l0);
        split2(kv.z, kv.w, h1, l1);
        *(uint2*)(KHg + toff + off) = make_uint2(h0, h1);
        *(uint2*)(KLg + toff + off) = make_uint2(l0, l1);
        float4 vv = Vt[i];
        split2(vv.x, vv.y, h0, l0);
        split2(vv.z, vv.w, h1, l1);
        *(uint2*)(VHg + toff + off) = make_uint2(h0, h1);
        *(uint2*)(VLg + toff + off) = make_uint2(l0, l1);
    }
}

// ---------------- prologue 2: pack mask into bitmaps ----------------
__global__ void __launch_bounds__(256)
maskbits(const int* __restrict__ Mask)
{
    const int kt = blockIdx.x, qt = blockIdx.y, b = blockIdx.z;
    const int t = threadIdx.x;
    const int row = t >> 1, h = t & 1;     // h: which 64-bit half of the 128 cols
    const int4* src = (const int4*)(Mask + ((size_t)b * Sc + qt * 128 + row) * Sc + kt * 128 + h * 64);
    u32 w0 = 0, w1 = 0;
    #pragma unroll
    for (int j4 = 0; j4 < 8; ++j4) {
        int4 v = src[j4];
        u32 bits = (v.x ? 1u : 0u) | (v.y ? 2u : 0u) | (v.z ? 4u : 0u) | (v.w ? 8u : 0u);
        w0 |= bits << (4 * j4);
    }
    #pragma unroll
    for (int j4 = 8; j4 < 16; ++j4) {
        int4 v = src[j4];
        u32 bits = (v.x ? 1u : 0u) | (v.y ? 2u : 0u) | (v.z ? 4u : 0u) | (v.w ? 8u : 0u);
        w1 |= bits << (4 * (j4 - 8));
    }
    *(uint2*)(MBg + (((size_t)(b * 16 + qt) * 16 + kt) * 128 + row) * 16 + h * 8) = make_uint2(w0, w1);
}

// cp.async one pre-split tile set (64KB KV + 2KB mask) into stage at smem addr sbst
__device__ __forceinline__ void load_stage(u32 sbst, int tid, size_t toff, size_t mtoff) {
    #pragma unroll
    for (int half = 0; half < 2; ++half) {
        u32 ci = ((u32)tid + 512u * half) * 16u;
        cpa16(sbst + 0     + ci, KHg + toff + ci);
        cpa16(sbst + 16384 + ci, KLg + toff + ci);
        cpa16(sbst + 32768 + ci, VHg + toff + ci);
        cpa16(sbst + 49152 + ci, VLg + toff + ci);
    }
    if (tid < 128) cpa16(sbst + 65536 + (u32)tid * 16u, MBg + mtoff + (u32)tid * 16u);
}

// ---------------- main kernel ----------------
__global__ void __launch_bounds__(NT, 1)
attn_mma(const float* __restrict__ Q, const float* __restrict__ K,
         const float* __restrict__ V, const int* __restrict__ Mask,
         float* __restrict__ Out)
{
    extern __shared__ char smc[];
    const u32 sb = smem_u32(smc);
    const int tid  = threadIdx.x;
    const int wid  = tid >> 5;
    const int lane = tid & 31;
    const int gid  = lane >> 2;
    const int tig  = lane & 3;
    const int wq   = wid & 7;     // q-row block (8 x 16 rows)
    const int ch   = wid >> 3;    // key-column half

    const int bh = blockIdx.y;
    const int b  = bh >> 4;
    const int q0 = blockIdx.x * 128;

    const float* Qg = Q + ((size_t)bh * Sc + q0) * 64;
    float*       Og = Out + ((size_t)bh * Sc + q0) * 64;
    const size_t tbase = (size_t)bh * 16 * TILE_B;
    const size_t mbase = ((size_t)(b * 16 + blockIdx.x) * 16) * MTILE_B;

    // ---- Q -> smem bf16 splits (pre-scaled by 1/8: exact) ----
    #pragma unroll
    for (int it = 0; it < 4; ++it) {
        int i = tid + NT * it;
        int r = i >> 4, c4 = i & 15;
        float4 v = ((const float4*)Qg)[i];
        u32 off = swz((u32)(r * 128 + c4 * 8));
        u32 h0, l0, h1, l1;
        split2(v.x * 0.125f, v.y * 0.125f, h0, l0);
        split2(v.z * 0.125f, v.w * 0.125f, h1, l1);
        *(uint2*)(smc + QH_OFF + off) = make_uint2(h0, h1);
        *(uint2*)(smc + QL_OFF + off) = make_uint2(l0, l1);
    }

    // ---- stage tile 0 ----
    load_stage(sb + STG_OFF, tid, tbase, mbase);
    CP_COMMIT();

    // ldmatrix per-lane address components
    const u32 aRB  = (u32)(16 * wq + (lane & 7) + ((lane >> 3) & 1) * 8) * 128;
    const u32 aKH  = (u32)(lane >> 4) * 16;
    const int bRow = (((lane >> 4) & 1) << 3) + (lane & 7);
    const u32 bKH  = (u32)((lane >> 3) & 1) * 16;
    const int vRow = (((lane >> 3) & 1) << 3) + (lane & 7);
    const u32 vDB  = (u32)(lane >> 4) * 16;
    const int kBase = 64 * ch;

    const int row0 = 16 * wq + gid;
    const int row1 = row0 + 8;
    const int mrowoff0 = row0 * 16 + ch * 8;   // byte offset of this thread's mask words
    const int mrowoff1 = row1 * 16 + ch * 8;

    CP_WAIT0();
    __syncthreads();   // Q smem + stage 0 visible

    float O[8][4];
    #pragma unroll
    for (int n = 0; n < 8; ++n)
        #pragma unroll
        for (int c = 0; c < 4; ++c) O[n][c] = 0.0f;
    float m0 = -1e30f, m1 = -1e30f, l0 = 0.0f, l1 = 0.0f;

    int stg = 0;

    for (int kt = 0; kt < NTILES; ++kt) {
        const u32 stqo = STG_OFF + (u32)stg * STG_SZ;
        const u32 stq  = sb + stqo;
        const u32 stqn = sb + STG_OFF + (u32)(stg ^ 1) * STG_SZ;

        // (i) prefetch next pre-split tile into other stage
        if (kt < NTILES - 1) {
            load_stage(stqn, tid, tbase + (size_t)(kt + 1) * TILE_B, mbase + (size_t)(kt + 1) * MTILE_B);
            CP_COMMIT();
        }

        // (ii) S = Q K^T over this warp's 64 key-cols
        float s[8][4];
        #pragma unroll
        for (int n = 0; n < 8; ++n)
            #pragma unroll
            for (int c = 0; c < 4; ++c) s[n][c] = 0.0f;

        #pragma unroll
        for (int k4 = 0; k4 < 4; ++k4) {
            u32 qoff = swz(aRB + (u32)k4 * 32 + aKH);
            u32 qh0, qh1, qh2, qh3, ql0, ql1, ql2, ql3;
            ldsm4(qh0, qh1, qh2, qh3, sb + QH_OFF + qoff);
            ldsm4(ql0, ql1, ql2, ql3, sb + QL_OFF + qoff);
            #pragma unroll
            for (int np = 0; np < 4; ++np) {
                u32 boff = swz((u32)(kBase + 16 * np + bRow) * 128 + (u32)k4 * 32 + bKH);
                u32 bh0, bh1, bh2, bh3, bl0, bl1, bl2, bl3;
                ldsm4(bh0, bh1, bh2, bh3, stq + 0     + boff);
                ldsm4(bl0, bl1, bl2, bl3, stq + 16384 + boff);
                mma_bf16(s[2 * np],     qh0, qh1, qh2, qh3, bh0, bh1);
                mma_bf16(s[2 * np + 1], qh0, qh1, qh2, qh3, bh2, bh3);
                mma_bf16(s[2 * np],     ql0, ql1, ql2, ql3, bh0, bh1);
                mma_bf16(s[2 * np + 1], ql0, ql1, ql2, ql3, bh2, bh3);
                mma_bf16(s[2 * np],     qh0, qh1, qh2, qh3, bl0, bl1);
                mma_bf16(s[2 * np + 1], qh0, qh1, qh2, qh3, bl2, bl3);
            }
        }

        // (iii) mask (smem bitmap) + online softmax (warp-local col-half)
        uint2 mw0 = *(const uint2*)(smc + stqo + 65536 + mrowoff0);
        uint2 mw1 = *(const uint2*)(smc + stqo + 65536 + mrowoff1);
        float mx0 = -1e30f, mx1 = -1e30f;
        #pragma unroll
        for (int n = 0; n < 8; ++n) {
            u32 sh = 8 * (n & 3) + 2 * tig;
            u32 wa = (n < 4) ? mw0.x : mw0.y;
            u32 wb = (n < 4) ? mw1.x : mw1.y;
            s[n][0] = ((wa >> sh) & 1u) ? s[n][0] : -32768.0f;
            s[n][1] = ((wa >> sh) & 2u) ? s[n][1] : -32768.0f;
            s[n][2] = ((wb >> sh) & 1u) ? s[n][2] : -32768.0f;
            s[n][3] = ((wb >> sh) & 2u) ? s[n][3] : -32768.0f;
            mx0 = fmaxf(mx0, fmaxf(s[n][0], s[n][1]));
            mx1 = fmaxf(mx1, fmaxf(s[n][2], s[n][3]));
        }
        mx0 = fmaxf(mx0, __shfl_xor_sync(0xffffffffu, mx0, 1));
        mx0 = fmaxf(mx0, __shfl_xor_sync(0xffffffffu, mx0, 2));
        mx1 = fmaxf(mx1, __shfl_xor_sync(0xffffffffu, mx1, 1));
        mx1 = fmaxf(mx1, __shfl_xor_sync(0xffffffffu, mx1, 2));

        float mn0 = fmaxf(m0, mx0), mn1 = fmaxf(m1, mx1);
        float alpha0 = ex2a((m0 - mn0) * LOG2E);
        float alpha1 = ex2a((m1 - mn1) * LOG2E);
        m0 = mn0; m1 = mn1;

        float sum0 = 0.0f, sum1 = 0.0f;
        #pragma unroll
        for (int n = 0; n < 8; ++n) {
            float p0 = ex2a((s[n][0] - mn0) * LOG2E);
            float p1 = ex2a((s[n][1] - mn0) * LOG2E);
            float p2 = ex2a((s[n][2] - mn1) * LOG2E);
            float p3 = ex2a((s[n][3] - mn1) * LOG2E);
            s[n][0] = p0; s[n][1] = p1; s[n][2] = p2; s[n][3] = p3;
            sum0 += p0 + p1; sum1 += p2 + p3;
        }
        sum0 += __shfl_xor_sync(0xffffffffu, sum0, 1);
        sum0 += __shfl_xor_sync(0xffffffffu, sum0, 2);
        sum1 += __shfl_xor_sync(0xffffffffu, sum1, 1);
        sum1 += __shfl_xor_sync(0xffffffffu, sum1, 2);
        l0 = l0 * alpha0 + sum0;
        l1 = l1 * alpha1 + sum1;

        #pragma unroll
        for (int n = 0; n < 8; ++n) {
            O[n][0] *= alpha0; O[n][1] *= alpha0;
            O[n][2] *= alpha1; O[n][3] *= alpha1;
        }

        // (iv) O += P V over this warp's 64 key-rows of V
        #pragma unroll
        for (int kk = 0; kk < 4; ++kk) {
            u32 ah0 = packbf2(s[2 * kk][0],     s[2 * kk][1]);
            u32 ah1 = packbf2(s[2 * kk][2],     s[2 * kk][3]);
            u32 ah2 = packbf2(s[2 * kk + 1][0], s[2 * kk + 1][1]);
            u32 ah3 = packbf2(s[2 * kk + 1][2], s[2 * kk + 1][3]);
            u32 al0 = packbf2(s[2 * kk][0] - bf_lo(ah0),     s[2 * kk][1] - bf_hi(ah0));
            u32 al1 = packbf2(s[2 * kk][2] - bf_lo(ah1),     s[2 * kk][3] - bf_hi(ah1));
            u32 al2 = packbf2(s[2 * kk + 1][0] - bf_lo(ah2), s[2 * kk + 1][1] - bf_hi(ah2));
            u32 al3 = packbf2(s[2 * kk + 1][2] - bf_lo(ah3), s[2 * kk + 1][3] - bf_hi(ah3));
            u32 vro = (u32)(kBase + 16 * kk + vRow) * 128;
            #pragma unroll
            for (int np = 0; np < 4; ++np) {
                u32 voff = swz(vro + (u32)np * 32 + vDB);
                u32 vh0, vh1, vh2, vh3, vl0, vl1, vl2, vl3;
                ldsm4t(vh0, vh1, vh2, vh3, stq + 32768 + voff);
                ldsm4t(vl0, vl1, vl2, vl3, stq + 49152 + voff);
                mma_bf16(O[2 * np],     ah0, ah1, ah2, ah3, vh0, vh1);
                mma_bf16(O[2 * np + 1], ah0, ah1, ah2, ah3, vh2, vh3);
                mma_bf16(O[2 * np],     al0, al1, al2, al3, vh0, vh1);
                mma_bf16(O[2 * np + 1], al0, al1, al2, al3, vh2, vh3);
                mma_bf16(O[2 * np],     ah0, ah1, ah2, ah3, vl0, vl1);
                mma_bf16(O[2 * np + 1], ah0, ah1, ah2, ah3, vl2, vl3);
            }
        }

        // (v) wait prefetch + single barrier per tile
        if (kt < NTILES - 1) CP_WAIT0();
        __syncthreads();
        stg ^= 1;
    }

    // ---- epilogue: merge col-halves (split-k combine), write ----
    float* MO = (float*)(smc + MRG_O);
    float* MM = (float*)(smc + MRG_M);
    float* ML = (float*)(smc + MRG_L);
    if (ch == 1) {
        if (tig == 0) {
            MM[row0] = m0; ML[row0] = l0;
            MM[row1] = m1; ML[row1] = l1;
        }
        #pragma unroll
        for (int n = 0; n < 8; ++n) {
            MO[row0 * 64 + 8 * n + 2 * tig]     = O[n][0];
            MO[row0 * 64 + 8 * n + 2 * tig + 1] = O[n][1];
            MO[row1 * 64 + 8 * n + 2 * tig]     = O[n][2];
            MO[row1 * 64 + 8 * n + 2 * tig + 1] = O[n][3];
        }
    }
    __syncthreads();
    if (ch == 0) {
        float mB0 = MM[row0], lB0 = ML[row0];
        float mB1 = MM[row1], lB1 = ML[row1];
        float mf0 = fmaxf(m0, mB0), mf1 = fmaxf(m1, mB1);
        float a0 = ex2a((m0 - mf0) * LOG2E), b0 = ex2a((mB0 - mf0) * LOG2E);
        float a1 = ex2a((m1 - mf1) * LOG2E), b1 = ex2a((mB1 - mf1) * LOG2E);
        float inv0 = 1.0f / (l0 * a0 + lB0 * b0);
        float inv1 = 1.0f / (l1 * a1 + lB1 * b1);
        float* o0 = Og + (size_t)row0 * 64 + 2 * tig;
        float* o1 = Og + (size_t)row1 * 64 + 2 * tig;
        #pragma unroll
        for (int n = 0; n < 8; ++n) {
            float w0 = (O[n][0] * a0 + MO[row0 * 64 + 8 * n + 2 * tig]     * b0) * inv0;
            float w1 = (O[n][1] * a0 + MO[row0 * 64 + 8 * n + 2 * tig + 1] * b0) * inv0;
            float w2 = (O[n][2] * a1 + MO[row1 * 64 + 8 * n + 2 * tig]     * b1) * inv1;
            float w3 = (O[n][3] * a1 + MO[row1 * 64 + 8 * n + 2 * tig + 1] * b1) * inv1;
            *(float2*)(o0 + 8 * n) = make_float2(w0, w1);
            *(float2*)(o1 + 8 * n) = make_float2(w2, w3);
        }
    }
}

extern "C" void kernel_launch(void* const* d_in, const int* in_sizes, int n_in,
                              void* d_out, int out_size)
{
    const float* Q    = (const float*)d_in[0];
    const float* K    = (const float*)d_in[1];
    const float* V    = (const float*)d_in[2];
    const int*   mask = (const int*)d_in[3];
    float* out = (float*)d_out;

    preconv<<<dim3(16, 32), 256>>>(K, V);
    maskbits<<<dim3(16, 16, 2), 256>>>(mask);

    cudaFuncSetAttribute(attn_mma, cudaFuncAttributeMaxDynamicSharedMemorySize, SMEM_BYTES);
    dim3 grid(Sc / 128, 32);
    attn_mma<<<grid, NT, SMEM_BYTES>>>(Q, K, V, mask, out);
}

// round 16
// speedup vs baseline: 1.2008x; 1.0024x over previous
#include <cuda_runtime.h>
#include <cstdint>

using u32 = unsigned int;

#define Sc 2048
#define NT 512
#define NTILES 16
#define LOG2E 1.4426950408889634f

// main-kernel smem: QH 0, QL 16384 (Q bf16 splits, 128x64)
// stage s at STG_OFF + s*STG_SZ: KH +0, KL +16384, VH +32768, VL +49152, MB +65536 (2KB)
#define QH_OFF 0
#define QL_OFF 16384
#define STG_OFF 32768
#define STG_SZ  67584
#define SMEM_BYTES (STG_OFF + 2 * STG_SZ)   /* 167936 */
// epilogue merge buffers alias stage 0
#define MRG_O STG_OFF
#define MRG_M (STG_OFF + 32768)
#define MRG_L (STG_OFF + 33280)

// pre-split, pre-swizzled K/V tiles: [bh][kt] -> 16384 bytes each
#define TILE_B 16384
__device__ static unsigned char KHg[32 * 16 * TILE_B];
__device__ static unsigned char KLg[32 * 16 * TILE_B];
__device__ static unsigned char VHg[32 * 16 * TILE_B];
__device__ static unsigned char VLg[32 * 16 * TILE_B];
// mask bitmaps: [b][qt][kt] -> 128 rows x 4 u32 = 2048 bytes
#define MTILE_B 2048
__device__ static unsigned char MBg[2 * 16 * 16 * MTILE_B];

__device__ __forceinline__ u32 swz(u32 x) { return x ^ ((x >> 3) & 0x70); }
__device__ __forceinline__ u32 smem_u32(const void* p) {
    u32 a;
    asm("{ .reg .u64 t; cvta.to.shared.u64 t, %1; cvt.u32.u64 %0, t; }" : "=r"(a) : "l"(p));
    return a;
}
__device__ __forceinline__ u32 packbf2(float lo, float hi) {   // lo -> low half
    u32 d; asm("cvt.rn.bf16x2.f32 %0, %1, %2;" : "=r"(d) : "f"(hi), "f"(lo)); return d;
}
__device__ __forceinline__ float bf_lo(u32 p) { return __uint_as_float(p << 16); }
__device__ __forceinline__ float bf_hi(u32 p) { return __uint_as_float(p & 0xffff0000u); }
__device__ __forceinline__ void split2(float a, float b, u32& h, u32& l) {
    h = packbf2(a, b);
    l = packbf2(a - bf_lo(h), b - bf_hi(h));
}
__device__ __forceinline__ float ex2a(float x) {
    float r; asm("ex2.approx.ftz.f32 %0, %1;" : "=f"(r) : "f"(x)); return r;
}
__device__ __forceinline__ void ldsm4(u32& r0, u32& r1, u32& r2, u32& r3, u32 a) {
    asm volatile("ldmatrix.sync.aligned.m8n8.x4.shared.b16 {%0,%1,%2,%3}, [%4];"
                 : "=r"(r0), "=r"(r1), "=r"(r2), "=r"(r3) : "r"(a));
}
__device__ __forceinline__ void ldsm4t(u32& r0, u32& r1, u32& r2, u32& r3, u32 a) {
    asm volatile("ldmatrix.sync.aligned.m8n8.x4.trans.shared.b16 {%0,%1,%2,%3}, [%4];"
                 : "=r"(r0), "=r"(r1), "=r"(r2), "=r"(r3) : "r"(a));
}
__device__ __forceinline__ void mma_bf16(float* d, u32 a0, u32 a1, u32 a2, u32 a3, u32 b0, u32 b1) {
    asm volatile("mma.sync.aligned.m16n8k16.row.col.f32.bf16.bf16.f32 "
                 "{%0,%1,%2,%3}, {%4,%5,%6,%7}, {%8,%9}, {%0,%1,%2,%3};"
                 : "+f"(d[0]), "+f"(d[1]), "+f"(d[2]), "+f"(d[3])
                 : "r"(a0), "r"(a1), "r"(a2), "r"(a3), "r"(b0), "r"(b1));
}
__device__ __forceinline__ void cpa16(u32 dst, const void* src) {
    asm volatile("cp.async.cg.shared.global [%0], [%1], 16;" :: "r"(dst), "l"(src));
}
#define CP_COMMIT() asm volatile("cp.async.commit_group;" ::: "memory")
#define CP_WAIT0()  asm volatile("cp.async.wait_group 0;" ::: "memory")

// ---------------- prologue 1: split + pre-swizzle K/V into gmem scratch ----------------
__global__ void __launch_bounds__(256)
preconv(const float* __restrict__ K, const float* __restrict__ V)
{
    const int kt = blockIdx.x;    // 0..15
    const int bh = blockIdx.y;    // 0..31
    const int tid = threadIdx.x;
    const size_t toff = ((size_t)bh * 16 + kt) * TILE_B;
    const float4* Kt = (const float4*)(K + ((size_t)bh * Sc + kt * 128) * 64);
    const float4* Vt = (const float4*)(V + ((size_t)bh * Sc + kt * 128) * 64);

    #pragma unroll
    for (int it = 0; it < 8; ++it) {
        int i = tid + 256 * it;            // float4 over [128 rows][16]
        int r = i >> 4, c4 = i & 15;
        u32 off = swz((u32)(r * 128 + c4 * 8));
        float4 kv = Kt[i];
        u32 h0, l0, h1, l1;
        split2(kv.x, kv.y, h0, l0);
        split2(kv.z, kv.w, h1, l1);
        *(uint2*)(KHg + toff + off) = make_uint2(h0, h1);
        *(uint2*)(KLg + toff + off) = make_uint2(l0, l1);
        float4 vv = Vt[i];
        split2(vv.x, vv.y, h0, l0);
        split2(vv.z, vv.w, h1, l1);
        *(uint2*)(VHg + toff + off) = make_uint2(h0, h1);
        *(uint2*)(VLg + toff + off) = make_uint2(l0, l1);
    }
}

// ---------------- prologue 2: pack mask into bitmaps ----------------
__global__ void __launch_bounds__(256)
maskbits(const int* __restrict__ Mask)
{
    const int kt = blockIdx.x, qt = blockIdx.y, b = blockIdx.z;
    const int t = threadIdx.x;
    const int row = t >> 1, h = t & 1;     // h: which 64-bit half of the 128 cols
    const int4* src = (const int4*)(Mask + ((size_t)b * Sc + qt * 128 + row) * Sc + kt * 128 + h * 64);
    u32 w0 = 0, w1 = 0;
    #pragma unroll
    for (int j4 = 0; j4 < 8; ++j4) {
        int4 v = src[j4];
        u32 bits = (v.x ? 1u : 0u) | (v.y ? 2u : 0u) | (v.z ? 4u : 0u) | (v.w ? 8u : 0u);
        w0 |= bits << (4 * j4);
    }
    #pragma unroll
    for (int j4 = 8; j4 < 16; ++j4) {
        int4 v = src[j4];
        u32 bits = (v.x ? 1u : 0u) | (v.y ? 2u : 0u) | (v.z ? 4u : 0u) | (v.w ? 8u : 0u);
        w1 |= bits << (4 * (j4 - 8));
    }
    *(uint2*)(MBg + (((size_t)(b * 16 + qt) * 16 + kt) * 128 + row) * 16 + h * 8) = make_uint2(w0, w1);
}

// cp.async one pre-split tile set (64KB KV + 2KB mask) into stage at smem addr sbst
__device__ __forceinline__ void load_stage(u32 sbst, int tid, size_t toff, size_t mtoff) {
    #pragma unroll
    for (int half = 0; half < 2; ++half) {
        u32 ci = ((u32)tid + 512u * half) * 16u;
        cpa16(sbst + 0     + ci, KHg + toff + ci);
        cpa16(sbst + 16384 + ci, KLg + toff + ci);
        cpa16(sbst + 32768 + ci, VHg + toff + ci);
        cpa16(sbst + 49152 + ci, VLg + toff + ci);
    }
    if (tid < 128) cpa16(sbst + 65536 + (u32)tid * 16u, MBg + mtoff + (u32)tid * 16u);
}

// ---------------- main kernel ----------------
__global__ void __launch_bounds__(NT, 1)
attn_mma(const float* __restrict__ Q, const float* __restrict__ K,
         const float* __restrict__ V, const int* __restrict__ Mask,
         float* __restrict__ Out)
{
    extern __shared__ char smc[];
    const u32 sb = smem_u32(smc);
    const int tid  = threadIdx.x;
    const int wid  = tid >> 5;
    const int lane = tid & 31;
    const int gid  = lane >> 2;
    const int tig  = lane & 3;
    const int wq   = wid & 7;     // q-row block (8 x 16 rows)
    const int ch   = wid >> 3;    // key-column half

    const int bh = blockIdx.y;
    const int b  = bh >> 4;
    const int q0 = blockIdx.x * 128;

    const float* Qg = Q + ((size_t)bh * Sc + q0) * 64;
    float*       Og = Out + ((size_t)bh * Sc + q0) * 64;
    const size_t tbase = (size_t)bh * 16 * TILE_B;
    const size_t mbase = ((size_t)(b * 16 + blockIdx.x) * 16) * MTILE_B;

    // ---- Q -> smem bf16 splits (pre-scaled by 1/8: exact) ----
    #pragma unroll
    for (int it = 0; it < 4; ++it) {
        int i = tid + NT * it;
        int r = i >> 4, c4 = i & 15;
        float4 v = ((const float4*)Qg)[i];
        u32 off = swz((u32)(r * 128 + c4 * 8));
        u32 h0, l0, h1, l1;
        split2(v.x * 0.125f, v.y * 0.125f, h0, l0);
        split2(v.z * 0.125f, v.w * 0.125f, h1, l1);
        *(uint2*)(smc + QH_OFF + off) = make_uint2(h0, h1);
        *(uint2*)(smc + QL_OFF + off) = make_uint2(l0, l1);
    }

    // ---- stage tile 0 ----
    load_stage(sb + STG_OFF, tid, tbase, mbase);
    CP_COMMIT();

    // ldmatrix per-lane address components
    const u32 aRB  = (u32)(16 * wq + (lane & 7) + ((lane >> 3) & 1) * 8) * 128;
    const u32 aKH  = (u32)(lane >> 4) * 16;
    const int bRow = (((lane >> 4) & 1) << 3) + (lane & 7);
    const u32 bKH  = (u32)((lane >> 3) & 1) * 16;
    const int vRow = (((lane >> 3) & 1) << 3) + (lane & 7);
    const u32 vDB  = (u32)(lane >> 4) * 16;
    const int kBase = 64 * ch;

    const int row0 = 16 * wq + gid;
    const int row1 = row0 + 8;
    const int mrowoff0 = row0 * 16 + ch * 8;   // byte offset of this thread's mask words
    const int mrowoff1 = row1 * 16 + ch * 8;

    CP_WAIT0();
    __syncthreads();   // Q smem + stage 0 visible

    float O[8][4];
    #pragma unroll
    for (int n = 0; n < 8; ++n)
        #pragma unroll
        for (int c = 0; c < 4; ++c) O[n][c] = 0.0f;
    float m0 = -1e30f, m1 = -1e30f, l0 = 0.0f, l1 = 0.0f;

    int stg = 0;

    for (int kt = 0; kt < NTILES; ++kt) {
        const u32 stqo = STG_OFF + (u32)stg * STG_SZ;
        const u32 stq  = sb + stqo;
        const u32 stqn = sb + STG_OFF + (u32)(stg ^ 1) * STG_SZ;

        // (i) prefetch next pre-split tile into other stage
        if (kt < NTILES - 1) {
            load_stage(stqn, tid, tbase + (size_t)(kt + 1) * TILE_B, mbase + (size_t)(kt + 1) * MTILE_B);
            CP_COMMIT();
        }

        // (ii) S = Q K^T over this warp's 64 key-cols
        float s[8][4];
        #pragma unroll
        for (int n = 0; n < 8; ++n)
            #pragma unroll
            for (int c = 0; c < 4; ++c) s[n][c] = 0.0f;

        #pragma unroll
        for (int k4 = 0; k4 < 4; ++k4) {
            u32 qoff = swz(aRB + (u32)k4 * 32 + aKH);
            u32 qh0, qh1, qh2, qh3, ql0, ql1, ql2, ql3;
            ldsm4(qh0, qh1, qh2, qh3, sb + QH_OFF + qoff);
            ldsm4(ql0, ql1, ql2, ql3, sb + QL_OFF + qoff);
            #pragma unroll
            for (int np = 0; np < 4; ++np) {
                u32 boff = swz((u32)(kBase + 16 * np + bRow) * 128 + (u32)k4 * 32 + bKH);
                u32 bh0, bh1, bh2, bh3, bl0, bl1, bl2, bl3;
                ldsm4(bh0, bh1, bh2, bh3, stq + 0     + boff);
                ldsm4(bl0, bl1, bl2, bl3, stq + 16384 + boff);
                mma_bf16(s[2 * np],     qh0, qh1, qh2, qh3, bh0, bh1);
                mma_bf16(s[2 * np + 1], qh0, qh1, qh2, qh3, bh2, bh3);
                mma_bf16(s[2 * np],     ql0, ql1, ql2, ql3, bh0, bh1);
                mma_bf16(s[2 * np + 1], ql0, ql1, ql2, ql3, bh2, bh3);
                mma_bf16(s[2 * np],     qh0, qh1, qh2, qh3, bl0, bl1);
                mma_bf16(s[2 * np + 1], qh0, qh1, qh2, qh3, bl2, bl3);
            }
        }

        // (iii) mask (smem bitmap) + online softmax (warp-local col-half)
        uint2 mw0 = *(const uint2*)(smc + stqo + 65536 + mrowoff0);
        uint2 mw1 = *(const uint2*)(smc + stqo + 65536 + mrowoff1);
        float mx0 = -1e30f, mx1 = -1e30f;
        #pragma unroll
        for (int n = 0; n < 8; ++n) {
            u32 sh = 8 * (n & 3) + 2 * tig;
            u32 wa = (n < 4) ? mw0.x : mw0.y;
            u32 wb = (n < 4) ? mw1.x : mw1.y;
            s[n][0] = ((wa >> sh) & 1u) ? s[n][0] : -32768.0f;
            s[n][1] = ((wa >> sh) & 2u) ? s[n][1] : -32768.0f;
            s[n][2] = ((wb >> sh) & 1u) ? s[n][2] : -32768.0f;
            s[n][3] = ((wb >> sh) & 2u) ? s[n][3] : -32768.0f;
            mx0 = fmaxf(mx0, fmaxf(s[n][0], s[n][1]));
            mx1 = fmaxf(mx1, fmaxf(s[n][2], s[n][3]));
        }
        mx0 = fmaxf(mx0, __shfl_xor_sync(0xffffffffu, mx0, 1));
        mx0 = fmaxf(mx0, __shfl_xor_sync(0xffffffffu, mx0, 2));
        mx1 = fmaxf(mx1, __shfl_xor_sync(0xffffffffu, mx1, 1));
        mx1 = fmaxf(mx1, __shfl_xor_sync(0xffffffffu, mx1, 2));

        float mn0 = fmaxf(m0, mx0), mn1 = fmaxf(m1, mx1);
        float alpha0 = ex2a((m0 - mn0) * LOG2E);
        float alpha1 = ex2a((m1 - mn1) * LOG2E);
        m0 = mn0; m1 = mn1;

        float sum0 = 0.0f, sum1 = 0.0f;
        #pragma unroll
        for (int n = 0; n < 8; ++n) {
            float p0 = ex2a((s[n][0] - mn0) * LOG2E);
            float p1 = ex2a((s[n][1] - mn0) * LOG2E);
            float p2 = ex2a((s[n][2] - mn1) * LOG2E);
            float p3 = ex2a((s[n][3] - mn1) * LOG2E);
            s[n][0] = p0; s[n][1] = p1; s[n][2] = p2; s[n][3] = p3;
            sum0 += p0 + p1; sum1 += p2 + p3;
        }
        sum0 += __shfl_xor_sync(0xffffffffu, sum0, 1);
        sum0 += __shfl_xor_sync(0xffffffffu, sum0, 2);
        sum1 += __shfl_xor_sync(0xffffffffu, sum1, 1);
        sum1 += __shfl_xor_sync(0xffffffffu, sum1, 2);
        l0 = l0 * alpha0 + sum0;
        l1 = l1 * alpha1 + sum1;

        #pragma unroll
        for (int n = 0; n < 8; ++n) {
            O[n][0] *= alpha0; O[n][1] *= alpha0;
            O[n][2] *= alpha1; O[n][3] *= alpha1;
        }

        // (iv) O += P V over this warp's 64 key-rows of V
        #pragma unroll
        for (int kk = 0; kk < 4; ++kk) {
            u32 ah0 = packbf2(s[2 * kk][0],     s[2 * kk][1]);
            u32 ah1 = packbf2(s[2 * kk][2],     s[2 * kk][3]);
            u32 ah2 = packbf2(s[2 * kk + 1][0], s[2 * kk + 1][1]);
            u32 ah3 = packbf2(s[2 * kk + 1][2], s[2 * kk + 1][3]);
            u32 al0 = packbf2(s[2 * kk][0] - bf_lo(ah0),     s[2 * kk][1] - bf_hi(ah0));
            u32 al1 = packbf2(s[2 * kk][2] - bf_lo(ah1),     s[2 * kk][3] - bf_hi(ah1));
            u32 al2 = packbf2(s[2 * kk + 1][0] - bf_lo(ah2), s[2 * kk + 1][1] - bf_hi(ah2));
            u32 al3 = packbf2(s[2 * kk + 1][2] - bf_lo(ah3), s[2 * kk + 1][3] - bf_hi(ah3));
            u32 vro = (u32)(kBase + 16 * kk + vRow) * 128;
            #pragma unroll
            for (int np = 0; np < 4; ++np) {
                u32 voff = swz(vro + (u32)np * 32 + vDB);
                u32 vh0, vh1, vh2, vh3, vl0, vl1, vl2, vl3;
                ldsm4t(vh0, vh1, vh2, vh3, stq + 32768 + voff);
                ldsm4t(vl0, vl1, vl2, vl3, stq + 49152 + voff);
                mma_bf16(O[2 * np],     ah0, ah1, ah2, ah3, vh0, vh1);
                mma_bf16(O[2 * np + 1], ah0, ah1, ah2, ah3, vh2, vh3);
                mma_bf16(O[2 * np],     al0, al1, al2, al3, vh0, vh1);
                mma_bf16(O[2 * np + 1], al0, al1, al2, al3, vh2, vh3);
                mma_bf16(O[2 * np],     ah0, ah1, ah2, ah3, vl0, vl1);
                mma_bf16(O[2 * np + 1], ah0, ah1, ah2, ah3, vl2, vl3);
            }
        }

        // (v) wait prefetch + single barrier per tile
        if (kt < NTILES - 1) CP_WAIT0();
        __syncthreads();
        stg ^= 1;
    }

    // ---- epilogue: merge col-halves (split-k combine), write ----
    float* MO = (float*)(smc + MRG_O);
    float* MM = (float*)(smc + MRG_M);
    float* ML = (float*)(smc + MRG_L);
    if (ch == 1) {
        if (tig == 0) {
            MM[row0] = m0; ML[row0] = l0;
            MM[row1] = m1; ML[row1] = l1;
        }
        #pragma unroll
        for (int n = 0; n < 8; ++n) {
            MO[row0 * 64 + 8 * n + 2 * tig]     = O[n][0];
            MO[row0 * 64 + 8 * n + 2 * tig + 1] = O[n][1];
            MO[row1 * 64 + 8 * n + 2 * tig]     = O[n][2];
            MO[row1 * 64 + 8 * n + 2 * tig + 1] = O[n][3];
        }
    }
    __syncthreads();
    if (ch == 0) {
        float mB0 = MM[row0], lB0 = ML[row0];
        float mB1 = MM[row1], lB1 = ML[row1];
        float mf0 = fmaxf(m0, mB0), mf1 = fmaxf(m1, mB1);
        float a0 = ex2a((m0 - mf0) * LOG2E), b0 = ex2a((mB0 - mf0) * LOG2E);
        float a1 = ex2a((m1 - mf1) * LOG2E), b1 = ex2a((mB1 - mf1) * LOG2E);
        float inv0 = 1.0f / (l0 * a0 + lB0 * b0);
        float inv1 = 1.0f / (l1 * a1 + lB1 * b1);
        float* o0 = Og + (size_t)row0 * 64 + 2 * tig;
        float* o1 = Og + (size_t)row1 * 64 + 2 * tig;
        #pragma unroll
        for (int n = 0; n < 8; ++n) {
            float w0 = (O[n][0] * a0 + MO[row0 * 64 + 8 * n + 2 * tig]     * b0) * inv0;
            float w1 = (O[n][1] * a0 + MO[row0 * 64 + 8 * n + 2 * tig + 1] * b0) * inv0;
            float w2 = (O[n][2] * a1 + MO[row1 * 64 + 8 * n + 2 * tig]     * b1) * inv1;
            float w3 = (O[n][3] * a1 + MO[row1 * 64 + 8 * n + 2 * tig + 1] * b1) * inv1;
            *(float2*)(o0 + 8 * n) = make_float2(w0, w1);
            *(float2*)(o1 + 8 * n) = make_float2(w2, w3);
        }
    }
}

extern "C" void kernel_launch(void* const* d_in, const int* in_sizes, int n_in,
                              void* d_out, int out_size)
{
    const float* Q    = (const float*)d_in[0];
    const float* K    = (const float*)d_in[1];
    const float* V    = (const float*)d_in[2];
    const int*   mask = (const int*)d_in[3];
    float* out = (float*)d_out;

    preconv<<<dim3(16, 32), 256>>>(K, V);
    maskbits<<<dim3(16, 16, 2), 256>>>(mask);

    cudaFuncSetAttribute(attn_mma, cudaFuncAttributeMaxDynamicSharedMemorySize, SMEM_BYTES);
    dim3 grid(Sc / 128, 32);
    attn_mma<<<grid, NT, SMEM_BYTES>>>(Q, K, V, mask, out);
}